// round 17
// baseline (speedup 1.0000x reference)
#include <cuda_runtime.h>

#define SEQ   96
#define PRED  16
#define HID   64
#define FEAT  7
#define BPB   4               // batches per block
#define NBLK  128             // 512/4 — one block per SM, single wave
#define NTHR  512
#define WIN   (SEQ + PRED)

typedef unsigned long long ull;

static __device__ __forceinline__ ull pack2(float a, float b){
    ull r; asm("mov.b64 %0, {%1, %2};" : "=l"(r) : "f"(a), "f"(b)); return r;
}
static __device__ __forceinline__ void unpack2(ull v, float &a, float &b){
    asm("mov.b64 {%0, %1}, %2;" : "=f"(a), "=f"(b) : "l"(v));
}
// d = a*b + d, packed f32x2 (Blackwell FFMA2), exact fp32 per lane
static __device__ __forceinline__ void ffma2(ull &d, ull a, ull b){
    asm("fma.rn.f32x2 %0, %1, %2, %0;" : "+l"(d) : "l"(a), "l"(b));
}

// s=1 -> sigmoid, s=2 -> tanh:  act = s/(1+exp(-s*x)) - (s-1)
static __device__ __forceinline__ float act(float x, float s, float sm1){
    float e = __expf(-s * x);
    return __fdividef(s, 1.0f + e) - sm1;
}
static __device__ __forceinline__ float tanhf_fast(float x){
    float e = __expf(-2.0f * x);
    return __fdividef(2.0f, 1.0f + e) - 1.0f;
}

__global__ void __launch_bounds__(NTHR, 1)
lstm_ar_kernel(const float* __restrict__ x,
               const float* __restrict__ W_ih,
               const float* __restrict__ W_hh,
               const float* __restrict__ b_ih,
               const float* __restrict__ b_hh,
               const float* __restrict__ fc_W,
               const float* __restrict__ fc_b,
               float* __restrict__ out)
{
    // sliding input window: [t][feat][b], b in [0,4)
    __shared__ float sh_xw[WIN * FEAT * BPB];
    // hidden state, double-buffered, batch-major: [buf][b][u]
    __shared__ float h_sh[2][BPB][HID];
    __shared__ float sh_fcW[FEAT * HID];
    __shared__ float sh_fcb[FEAT];

    const int tid = threadIdx.x;            // 0..511
    const int bp  = tid >> 8;               // batch pair (half; 8 warps each)
    const int r   = tid & 255;              // r = u*4 + g  (4 gates adjacent in lane space)
    const int u   = r >> 2;                 // hidden unit
    const int g   = r & 3;                  // gate 0..3 = i,f,g,o
    const int row = g * HID + u;            // W row for this thread
    const int b0  = blockIdx.x * BPB;
    const int barid = 1 + bp;               // named barrier per independent half
    const int tl  = tid & 255;              // index within half

    // ---------------- one-time init ----------------
    for (int i = tid; i < SEQ * FEAT * BPB; i += NTHR){
        int b = i & 3;
        int q = i >> 2;
        int f = q % FEAT;
        int t = q / FEAT;
        sh_xw[(t * FEAT + f) * BPB + b] =
            x[(size_t)(b0 + b) * SEQ * FEAT + t * FEAT + f];
    }
    for (int i = tid; i < FEAT * HID; i += NTHR) sh_fcW[i] = fc_W[i];
    if (tid < FEAT) sh_fcb[tid] = fc_b[tid];
    {
        float* hz = &h_sh[0][0][0];
        for (int i = tid; i < 2 * BPB * HID; i += NTHR) hz[i] = 0.0f;
    }

    // W_hh row as natural column-pairs: whh[c] = (W[2c], W[2c+1]) — 32 u64 = 64 regs
    ull whh[HID / 2];
    {
        const ull* wr = reinterpret_cast<const ull*>(W_hh + (size_t)row * HID);
        #pragma unroll
        for (int c = 0; c < HID / 2; c++) whh[c] = wr[c];
    }
    // W_ih row, splatted for batch-pair f32x2 x-projection
    ull wih2[FEAT];
    #pragma unroll
    for (int f = 0; f < FEAT; f++){
        float w = W_ih[row * FEAT + f];
        wih2[f] = pack2(w, w);
    }
    const float bias = b_ih[row] + b_hh[row];
    const ull bias2 = pack2(bias, bias);

    const float s_act = (g == 2) ? 2.0f : 1.0f;   // cell gate uses tanh
    const float s_m1  = s_act - 1.0f;

    float c_reg = 0.0f;        // finishers g<2 own cell state of (batch 2bp+g, unit u)
    int p = 0;

    __syncthreads();           // only global sync: after init

    // ------- 16 AR iterations x 96 steps; the two halves never re-couple -------
    for (int k = 0; k < PRED; k++){
        // prefetch x-projection (bias included) for step t=0, batch-pair packed
        ull xacc = bias2;
        {
            const float* xrow = &sh_xw[k * FEAT * BPB + 2 * bp];
            #pragma unroll
            for (int f = 0; f < FEAT; f++){
                ull xx = *reinterpret_cast<const ull*>(xrow + f * BPB);
                ffma2(xacc, xx, wih2[f]);
            }
        }

        for (int t = 0; t < SEQ; t++){
            // ---- consume prefetched x-projection ----
            float xe_, xo_;
            unpack2(xacc, xe_, xo_);

            // ---- h-dot: 1 row x 2 batches over 64 cols (64 FFMA2) ----
            ull acc0 = pack2(xe_, 0.0f);
            ull acc1 = pack2(xo_, 0.0f);
            const ulonglong2* hE =
                reinterpret_cast<const ulonglong2*>(&h_sh[p][2*bp    ][0]);
            const ulonglong2* hO =
                reinterpret_cast<const ulonglong2*>(&h_sh[p][2*bp + 1][0]);
            #pragma unroll
            for (int c = 0; c < 16; c++){
                ulonglong2 u0 = hE[c];          // cols 4c..4c+3, batch even (broadcast)
                ulonglong2 u1 = hO[c];          // batch odd
                ffma2(acc0, u0.x, whh[2*c]);
                ffma2(acc0, u0.y, whh[2*c+1]);
                ffma2(acc1, u1.x, whh[2*c]);
                ffma2(acc1, u1.y, whh[2*c+1]);
            }
            float e, o;
            float v0, v1;
            unpack2(acc0, e, o); v0 = e + o;    // this gate, batch even
            unpack2(acc1, e, o); v1 = e + o;    // this gate, batch odd

            // ---- activate own gate (branchless per-lane type) ----
            v0 = act(v0, s_act, s_m1);
            v1 = act(v1, s_act, s_m1);

            // ---- 3-shfl butterfly across the 4 gate lanes of unit u ----
            // after xor1: lane0 {i_e, f_e}, lane1 {f_o, i_o}, lane2 {g_e, o_e}, lane3 {o_o, g_o}
            float s1    = (g & 1) ? v0 : v1;
            float r1    = __shfl_xor_sync(0xffffffffu, s1, 1);
            float keepA = (g & 1) ? v1 : v0;
            float t1    = __shfl_xor_sync(0xffffffffu, keepA, 2);
            float t2    = __shfl_xor_sync(0xffffffffu, r1, 2);

            // ---- finishers: g=0 -> batch even, g=1 -> batch odd ----
            if (g < 2){
                float gi = g ? r1    : keepA;
                float gf = g ? keepA : r1;
                float gg = g ? t2    : t1;
                float go = g ? t1    : t2;
                c_reg = fmaf(gf, c_reg, gi * gg);
                h_sh[p ^ 1][2*bp + g][u] = go * tanhf_fast(c_reg);
            }

            // ---- prefetch next step's x-projection inside the barrier shadow ----
            if (t < SEQ - 1){
                xacc = bias2;
                const float* xrow = &sh_xw[(k + t + 1) * FEAT * BPB + 2 * bp];
                #pragma unroll
                for (int f = 0; f < FEAT; f++){
                    ull xx = *reinterpret_cast<const ull*>(xrow + f * BPB);
                    ffma2(xacc, xx, wih2[f]);
                }
            }

            asm volatile("bar.sync %0, 256;" :: "r"(barid) : "memory");
            p ^= 1;
        }

        // ---- per-half fc head: this half's 2 batches only ----
        if (tl < FEAT * 2){
            int bl = tl / FEAT;                // 0..1 within the half
            int o2 = tl - bl * FEAT;
            int b  = 2 * bp + bl;
            float acc = sh_fcb[o2];
            #pragma unroll
            for (int jj = 0; jj < HID; jj++)
                acc += h_sh[p][b][jj] * sh_fcW[o2 * HID + jj];
            out[(size_t)(b0 + b) * PRED * FEAT + k * FEAT + o2] = acc;
            sh_xw[((SEQ + k) * FEAT + o2) * BPB + b] = acc;
        }
        asm volatile("bar.sync %0, 256;" :: "r"(barid) : "memory");
    }
}

extern "C" void kernel_launch(void* const* d_in, const int* in_sizes, int n_in,
                              void* d_out, int out_size)
{
    const float* x    = (const float*)d_in[0];
    const float* W_ih = (const float*)d_in[1];
    const float* W_hh = (const float*)d_in[2];
    const float* b_ih = (const float*)d_in[3];
    const float* b_hh = (const float*)d_in[4];
    const float* fc_W = (const float*)d_in[5];
    const float* fc_b = (const float*)d_in[6];
    float* out = (float*)d_out;

    lstm_ar_kernel<<<NBLK, NTHR>>>(x, W_ih, W_hh, b_ih, b_hh, fc_W, fc_b, out);
}